// round 14
// baseline (speedup 1.0000x reference)
#include <cuda_runtime.h>
#include <cuda_bf16.h>
#include <cuda_fp16.h>
#include <cstdint>

#define BN    32
#define LN    36864
#define CN    16
#define KN    24
#define LOUT  1536
#define DN    512
#define CKN   384
#define MTOT  (BN * LOUT)      // 49152

// single TU-wide dynamic smem symbol
extern __shared__ char smem_c[];

// ---------------- global scratch ---------------------------------------------
__device__ __half g_A [(size_t)MTOT * 384];   // sampled values, ck = c*24+k
__device__ __half g_B [(size_t)DN * 384];     // w_def fp16, ck = c*24+k
__device__ __half g_W [(size_t)48 * 384];     // w_off fp16, TRANSPOSED ck' = k*16+c
__device__ float  g_Off[(size_t)MTOT * 48];   // predicted offsets (+bias)

// ---------------- PTX helpers ------------------------------------------------
__device__ __forceinline__ uint32_t smem_u32(const void* p) {
    return (uint32_t)__cvta_generic_to_shared(p);
}

#define SWZ128(off) ((off) ^ (((off) >> 3) & 0x70))

__device__ __forceinline__ void cp_async16(uint32_t saddr, const void* gptr) {
    asm volatile("cp.async.cg.shared.global [%0], [%1], 16;" :: "r"(saddr), "l"(gptr));
}
#define CP_COMMIT() asm volatile("cp.async.commit_group;" ::: "memory")
#define CP_WAIT(N)  asm volatile("cp.async.wait_group %0;" :: "n"(N) : "memory")

__device__ __forceinline__ void ldm_x4(uint32_t& r0, uint32_t& r1, uint32_t& r2,
                                       uint32_t& r3, uint32_t addr) {
    asm volatile("ldmatrix.sync.aligned.m8n8.x4.shared.b16 {%0,%1,%2,%3}, [%4];"
                 : "=r"(r0), "=r"(r1), "=r"(r2), "=r"(r3) : "r"(addr));
}
__device__ __forceinline__ void mma_fp16(float* d, const uint32_t* a, const uint32_t* b) {
    asm volatile(
        "mma.sync.aligned.m16n8k16.row.col.f32.f16.f16.f32 "
        "{%0,%1,%2,%3}, {%4,%5,%6,%7}, {%8,%9}, {%0,%1,%2,%3};"
        : "+f"(d[0]), "+f"(d[1]), "+f"(d[2]), "+f"(d[3])
        : "r"(a[0]), "r"(a[1]), "r"(a[2]), "r"(a[3]), "r"(b[0]), "r"(b[1]));
}
__device__ __forceinline__ uint32_t h2u(__half2 h) { return *(uint32_t*)&h; }

// =============================================================================
// Kernel S: w_def -> g_B (fp16, layout kept) ; w_off -> g_W (fp16, k-major)
// =============================================================================
__global__ void split_weights_kernel(const float* __restrict__ w_def,
                                     const float* __restrict__ w_off) {
    int idx = blockIdx.x * blockDim.x + threadIdx.x;
    if (idx >= (DN + 48) * CKN) return;
    if (idx < DN * CKN) {
        g_B[idx] = __float2half_rn(__ldg(&w_def[idx]));
    } else {
        int j = idx - DN * CKN;
        int o = j / CKN, r = j % CKN;
        int k = r >> 4, c = r & 15;               // write ck' = k*16+c
        g_W[j] = __float2half_rn(__ldg(&w_off[o * CKN + c * KN + k]));
    }
}

// =============================================================================
// Kernel O: offset GEMM  g_Off[49152][48] = x_win x g_W^T + b_off
// A = x read DIRECTLY (fp32 -> fp16 in-kernel). CTA 128m x 48n, k-chunk 64.
// =============================================================================
#define NTHRO 256
#define OCHUNK 6
// smem bytes: A[2][16384] at 0, B[2][6144] at 32768
#define SOA0 0
#define SOA1 16384
#define SOB0 32768
#define SOB1 (32768 + 6144)
#define SO_TOT (32768 + 12288)      // 45056

__global__ __launch_bounds__(NTHRO, 2)
void offset_gemm_kernel(const float* __restrict__ x,
                        const float* __restrict__ b_off)
{
    const uint32_t sb = smem_u32(smem_c);
    const int t    = threadIdx.x;
    const int wid  = t >> 5;
    const int lane = t & 31;
    const int m0g  = blockIdx.x * 128;
    const int wm   = wid * 16;

    float acc[6][4];
    #pragma unroll
    for (int j = 0; j < 6; j++)
        #pragma unroll
        for (int e = 0; e < 4; e++) acc[j][e] = 0.0f;

    float4 pa[8];     // prefetched A f32 (4 units x 8 floats)

    auto ldgA = [&](int c) {
        int kOff = 64 * c;
        #pragma unroll
        for (int i = 0; i < 4; i++) {
            int idx = t + i * NTHRO;
            int row = idx >> 3, c16 = idx & 7;
            const float4* src = (const float4*)(x + (size_t)(m0g + row) * 384 + kOff + c16 * 8);
            pa[2 * i]     = __ldg(src);
            pa[2 * i + 1] = __ldg(src + 1);
        }
    };
    auto stsA = [&](int buf) {
        char* base = smem_c + (buf ? SOA1 : SOA0);
        #pragma unroll
        for (int i = 0; i < 4; i++) {
            int idx = t + i * NTHRO;
            int row = idx >> 3, c16 = idx & 7;
            uint4 u;
            u.x = h2u(__floats2half2_rn(pa[2 * i].x,     pa[2 * i].y));
            u.y = h2u(__floats2half2_rn(pa[2 * i].z,     pa[2 * i].w));
            u.z = h2u(__floats2half2_rn(pa[2 * i + 1].x, pa[2 * i + 1].y));
            u.w = h2u(__floats2half2_rn(pa[2 * i + 1].z, pa[2 * i + 1].w));
            *(uint4*)(base + SWZ128(row * 128 + c16 * 16)) = u;
        }
    };
    auto cpB = [&](int c) {
        int kOff = 64 * c;
        uint32_t sB = sb + ((c & 1) ? SOB1 : SOB0);
        {
            int idx = t;
            int row = idx >> 3, c16 = idx & 7;
            cp_async16(sB + SWZ128(row * 128 + c16 * 16),
                       g_W + (size_t)row * 384 + kOff + c16 * 8);
        }
        if (t < 128) {
            int idx = t + 256;
            int row = idx >> 3, c16 = idx & 7;
            cp_async16(sB + SWZ128(row * 128 + c16 * 16),
                       g_W + (size_t)row * 384 + kOff + c16 * 8);
        }
    };

    // preamble: stage chunk 0
    ldgA(0); stsA(0);
    cpB(0); CP_COMMIT();

    for (int c = 0; c < OCHUNK; c++) {
        if (c + 1 < OCHUNK) {
            ldgA(c + 1);
            cpB(c + 1); CP_COMMIT();
            CP_WAIT(1);
        } else {
            CP_WAIT(0);
        }
        __syncthreads();       // A(c) STS + B(c) cp.async visible

        int buf = c & 1;
        uint32_t sA = sb + (buf ? SOA1 : SOA0);
        uint32_t sB = sb + (buf ? SOB1 : SOB0);

        #pragma unroll
        for (int k16 = 0; k16 < 4; k16++) {
            int kb = k16 * 32;
            uint32_t a[4];
            {
                int row  = wm + (lane & 15);
                int colb = kb + ((lane & 16) ? 16 : 0);
                ldm_x4(a[0], a[1], a[2], a[3], sA + SWZ128(row * 128 + colb));
            }
            uint32_t bf[6][2];
            #pragma unroll
            for (int p = 0; p < 3; p++) {
                int grp  = lane >> 3;
                int nt   = p * 2 + (grp >> 1);       // 0..5
                int half = grp & 1;
                int row  = nt * 8 + (lane & 7);      // 0..47
                int colb = kb + half * 16;
                uint32_t r0, r1, r2, r3;
                ldm_x4(r0, r1, r2, r3, sB + SWZ128(row * 128 + colb));
                bf[p * 2][0] = r0;  bf[p * 2][1] = r1;
                bf[p * 2 + 1][0] = r2;  bf[p * 2 + 1][1] = r3;
            }
            #pragma unroll
            for (int j = 0; j < 6; j++)
                mma_fp16(acc[j], a, bf[j]);
        }
        if (c + 1 < OCHUNK) stsA((c + 1) & 1);
        // RACE FIX (round 13 regression): reads of buffer (c&1) above must
        // complete in ALL threads before iteration c+1 issues cp.async writes
        // into buffer ((c+2)&1 == c&1). Round 12 had this barrier; restoring.
        __syncthreads();
    }

    // epilogue: + b_off, store float2
    #pragma unroll
    for (int j = 0; j < 6; j++) {
        int n = j * 8 + (lane & 3) * 2;
        float2 bias = __ldg((const float2*)(b_off + n));
        int m = m0g + wm + (lane >> 2);
        *(float2*)(g_Off + (size_t)m * 48 + n) =
            make_float2(acc[j][0] + bias.x, acc[j][1] + bias.y);
        *(float2*)(g_Off + (size_t)(m + 8) * 48 + n) =
            make_float2(acc[j][2] + bias.x, acc[j][3] + bias.y);
    }
}

// =============================================================================
// Kernel V: sampling — register-resident gather, direct coalesced fp16 stores
// CTA = 64 m rows, 256 threads: thread = (m_local = t>>2, cg = t&3).
// =============================================================================
#define NTHRV 256
#define SMV_TOT (64 * 48 * 4)      // 12288 B offset stage

__global__ __launch_bounds__(NTHRV, 1)
void sampling_kernel(const float* __restrict__ x)
{
    float* s_off = (float*)smem_c;
    const int t = threadIdx.x;
    const size_t mbase = (size_t)blockIdx.x * 64;
    const int b = (int)(mbase / LOUT);
    const int lout0 = (int)(mbase % LOUT);
    const float* xb = x + (size_t)b * LN * CN;

    // stage 64 x 48 offsets (coalesced float4)
    {
        const float4* src = (const float4*)(g_Off + mbase * 48);
        float4* dst = (float4*)s_off;
        #pragma unroll
        for (int i = 0; i < 3; i++)
            dst[t + i * NTHRV] = __ldg(&src[t + i * NTHRV]);
    }
    __syncthreads();

    const int m  = t >> 2;        // 0..63
    const int cg = t & 3;         // channel group (4 channels)
    const int base_l = (lout0 + m) * KN;
    const float* srow = s_off + m * 48;

    uint32_t outw[4][12];         // [c_loc][k-pair] packed half2

    #pragma unroll
    for (int kp = 0; kp < 12; kp++) {
        float f[2][4];
        #pragma unroll
        for (int j = 0; j < 2; j++) {
            int k = 2 * kp + j;
            float dy = srow[2 * k];
            float dx = srow[2 * k + 1];
            float wy = fmaxf(0.0f, 1.0f - fabsf(dy));
            float px = (float)(base_l + k) + dx;
            bool valid = (px > -1.0f) && (px < (float)LN);
            float x0f = floorf(px);
            float lw = px - x0f;
            int i0 = (int)x0f;
            int i1 = i0 + 1;
            float w0 = (valid && i0 >= 0 && i0 < LN) ? (1.0f - lw) * wy : 0.0f;
            float w1 = (valid && i1 >= 0 && i1 < LN) ? lw * wy : 0.0f;
            int i0c = min(max(i0, 0), LN - 1);
            int i1c = min(max(i1, 0), LN - 1);
            float4 v0 = __ldg((const float4*)(xb + (size_t)i0c * CN) + cg);
            float4 v1 = __ldg((const float4*)(xb + (size_t)i1c * CN) + cg);
            f[j][0] = v0.x * w0 + v1.x * w1;
            f[j][1] = v0.y * w0 + v1.y * w1;
            f[j][2] = v0.z * w0 + v1.z * w1;
            f[j][3] = v0.w * w0 + v1.w * w1;
        }
        #pragma unroll
        for (int cl = 0; cl < 4; cl++)
            outw[cl][kp] = h2u(__floats2half2_rn(f[0][cl], f[1][cl]));
    }

    // store: per channel c = cg*4+cl, run of 24 halfs at g_A[m][(cg*4+cl)*24]
    __half* garow = g_A + (mbase + m) * 384 + cg * 96;
    #pragma unroll
    for (int cl = 0; cl < 4; cl++) {
        uint4* dst = (uint4*)(garow + cl * 24);
        dst[0] = make_uint4(outw[cl][0], outw[cl][1], outw[cl][2],  outw[cl][3]);
        dst[1] = make_uint4(outw[cl][4], outw[cl][5], outw[cl][6],  outw[cl][7]);
        dst[2] = make_uint4(outw[cl][8], outw[cl][9], outw[cl][10], outw[cl][11]);
    }
}

// =============================================================================
// Kernel G: main GEMM  out[49152][512] = g_A x g_B^T  (6 chunks, single fp16)
// =============================================================================
#define NTHR2 256
#define NCHUNK 6
#define SM2A0 0
#define SM2B0 16384
#define SM2A1 32768
#define SM2B1 49152
#define SM2_TOT 65536

__global__ __launch_bounds__(NTHR2, 2)
void gemm_mma_kernel(const float* __restrict__ b_def, float* __restrict__ out)
{
    const uint32_t sb = smem_u32(smem_c);
    const int t    = threadIdx.x;
    const int wid  = t >> 5;
    const int lane = t & 31;
    const int m0g  = blockIdx.x * 128;
    const int n0g  = blockIdx.y * 128;

    const int wm = (wid >> 2) * 64;
    const int wn = (wid & 3) * 32;

    const int prow = t >> 3;
    const int pc16 = t & 7;

    float acc[4][4][4];
    #pragma unroll
    for (int i = 0; i < 4; i++)
        #pragma unroll
        for (int j = 0; j < 4; j++)
            #pragma unroll
            for (int e = 0; e < 4; e++) acc[i][j][e] = 0.0f;

    auto prefetch = [&](int c) {
        int buf = c & 1;
        int kOff = 64 * c;
        uint32_t sA = sb + (buf ? SM2A1 : SM2A0);
        uint32_t sB = sb + (buf ? SM2B1 : SM2B0);
        #pragma unroll
        for (int i = 0; i < 4; i++) {
            int row = prow + i * 32;
            cp_async16(sA + SWZ128(row * 128 + pc16 * 16),
                       g_A + (size_t)(m0g + row) * 384 + kOff + pc16 * 8);
        }
        #pragma unroll
        for (int i = 0; i < 4; i++) {
            int row = prow + i * 32;
            cp_async16(sB + SWZ128(row * 128 + pc16 * 16),
                       g_B + (size_t)(n0g + row) * 384 + kOff + pc16 * 8);
        }
    };

    prefetch(0);
    CP_COMMIT();

    for (int c = 0; c < NCHUNK; c++) {
        if (c + 1 < NCHUNK) {
            prefetch(c + 1);
            CP_COMMIT();
            CP_WAIT(1);
        } else {
            CP_WAIT(0);
        }
        __syncthreads();

        int buf = c & 1;
        uint32_t sA = sb + (buf ? SM2A1 : SM2A0);
        uint32_t sB = sb + (buf ? SM2B1 : SM2B0);

        #pragma unroll
        for (int k16 = 0; k16 < 4; k16++) {
            int kb = k16 * 32;
            uint32_t a[4][4];
            #pragma unroll
            for (int i = 0; i < 4; i++) {
                int row  = wm + i * 16 + (lane & 15);
                int colb = kb + ((lane & 16) ? 16 : 0);
                ldm_x4(a[i][0], a[i][1], a[i][2], a[i][3],
                       sA + SWZ128(row * 128 + colb));
            }
            uint32_t bf[4][2];
            #pragma unroll
            for (int p = 0; p < 2; p++) {
                int grp  = lane >> 3;
                int nt   = p * 2 + (grp >> 1);
                int half = grp & 1;
                int row  = wn + nt * 8 + (lane & 7);
                int colb = kb + half * 16;
                uint32_t r0, r1, r2, r3;
                ldm_x4(r0, r1, r2, r3, sB + SWZ128(row * 128 + colb));
                bf[p * 2][0] = r0;  bf[p * 2][1] = r1;
                bf[p * 2 + 1][0] = r2;  bf[p * 2 + 1][1] = r3;
            }
            #pragma unroll
            for (int i = 0; i < 4; i++)
                #pragma unroll
                for (int j = 0; j < 4; j++)
                    mma_fp16(acc[i][j], a[i], bf[j]);
        }
        __syncthreads();
    }

    #pragma unroll
    for (int j = 0; j < 4; j++) {
        int n = n0g + wn + j * 8 + (lane & 3) * 2;
        float2 bias = __ldg((const float2*)(b_def + n));
        #pragma unroll
        for (int i = 0; i < 4; i++) {
            int m = m0g + wm + i * 16 + (lane >> 2);
            float2 v0 = make_float2(acc[i][j][0] + bias.x, acc[i][j][1] + bias.y);
            float2 v1 = make_float2(acc[i][j][2] + bias.x, acc[i][j][3] + bias.y);
            *(float2*)(out + (size_t)m * DN + n) = v0;
            *(float2*)(out + (size_t)(m + 8) * DN + n) = v1;
        }
    }
}

// =============================================================================
extern "C" void kernel_launch(void* const* d_in, const int* in_sizes, int n_in,
                              void* d_out, int out_size)
{
    const float* x     = (const float*)d_in[0];
    const float* w_off = (const float*)d_in[1];
    const float* b_off = (const float*)d_in[2];
    const float* w_def = (const float*)d_in[3];
    const float* b_def = (const float*)d_in[4];
    float* out = (float*)d_out;

    static bool attr_set = false;
    if (!attr_set) {
        cudaFuncSetAttribute(gemm_mma_kernel,
                             cudaFuncAttributeMaxDynamicSharedMemorySize, SM2_TOT);
        attr_set = true;
    }

    split_weights_kernel<<<((DN + 48) * CKN + 255) / 256, 256>>>(w_def, w_off);
    offset_gemm_kernel<<<MTOT / 128, NTHRO, SO_TOT>>>(x, b_off);
    sampling_kernel<<<MTOT / 64, NTHRV, SMV_TOT>>>(x);
    dim3 grid2(MTOT / 128, DN / 128);
    gemm_mma_kernel<<<grid2, NTHR2, SM2_TOT>>>(b_def, out);
}

// round 15
// speedup vs baseline: 1.0471x; 1.0471x over previous
#include <cuda_runtime.h>
#include <cuda_bf16.h>
#include <cuda_fp16.h>
#include <cstdint>

#define BN    32
#define LN    36864
#define CN    16
#define KN    24
#define LOUT  1536
#define DN    512
#define CKN   384
#define MTOT  (BN * LOUT)      // 49152

// single TU-wide dynamic smem symbol
extern __shared__ char smem_c[];

// ---------------- global scratch (ALL k-major: ck' = k*16 + c) ---------------
__device__ __half g_A [(size_t)MTOT * 384];   // sampled values, k-major
__device__ __half g_B [(size_t)DN * 384];     // w_def fp16, k-major
__device__ __half g_W [(size_t)48 * 384];     // w_off fp16, k-major
__device__ float  g_Off[(size_t)MTOT * 48];   // predicted offsets (+bias)

// ---------------- PTX helpers ------------------------------------------------
__device__ __forceinline__ uint32_t smem_u32(const void* p) {
    return (uint32_t)__cvta_generic_to_shared(p);
}

#define SWZ128(off) ((off) ^ (((off) >> 3) & 0x70))

__device__ __forceinline__ void cp_async16(uint32_t saddr, const void* gptr) {
    asm volatile("cp.async.cg.shared.global [%0], [%1], 16;" :: "r"(saddr), "l"(gptr));
}
#define CP_COMMIT() asm volatile("cp.async.commit_group;" ::: "memory")
#define CP_WAIT(N)  asm volatile("cp.async.wait_group %0;" :: "n"(N) : "memory")

__device__ __forceinline__ void ldm_x4(uint32_t& r0, uint32_t& r1, uint32_t& r2,
                                       uint32_t& r3, uint32_t addr) {
    asm volatile("ldmatrix.sync.aligned.m8n8.x4.shared.b16 {%0,%1,%2,%3}, [%4];"
                 : "=r"(r0), "=r"(r1), "=r"(r2), "=r"(r3) : "r"(addr));
}
__device__ __forceinline__ void mma_fp16(float* d, const uint32_t* a, const uint32_t* b) {
    asm volatile(
        "mma.sync.aligned.m16n8k16.row.col.f32.f16.f16.f32 "
        "{%0,%1,%2,%3}, {%4,%5,%6,%7}, {%8,%9}, {%0,%1,%2,%3};"
        : "+f"(d[0]), "+f"(d[1]), "+f"(d[2]), "+f"(d[3])
        : "r"(a[0]), "r"(a[1]), "r"(a[2]), "r"(a[3]), "r"(b[0]), "r"(b[1]));
}
__device__ __forceinline__ uint32_t h2u(__half2 h) { return *(uint32_t*)&h; }

// =============================================================================
// Kernel S: transpose w_def -> g_B (k-major) ; w_off -> g_W (k-major)
// =============================================================================
__global__ void split_weights_kernel(const float* __restrict__ w_def,
                                     const float* __restrict__ w_off) {
    int idx = blockIdx.x * blockDim.x + threadIdx.x;
    if (idx >= (DN + 48) * CKN) return;
    if (idx < DN * CKN) {
        int d = idx / CKN, r = idx % CKN;
        int k = r >> 4, c = r & 15;               // dst ck' = k*16+c
        g_B[idx] = __float2half_rn(__ldg(&w_def[d * CKN + c * KN + k]));
    } else {
        int j = idx - DN * CKN;
        int o = j / CKN, r = j % CKN;
        int k = r >> 4, c = r & 15;
        g_W[j] = __float2half_rn(__ldg(&w_off[o * CKN + c * KN + k]));
    }
}

// =============================================================================
// Kernel O: offset GEMM  g_Off[49152][48] = x_win x g_W^T + b_off
// A = x read DIRECTLY (naturally k-major). CTA 128m x 48n, k-chunk 64.
// Single barrier per chunk: wait -> sync -> issue next -> compute -> stsA.
// =============================================================================
#define NTHRO 256
#define OCHUNK 6
// smem bytes: A[2][16384] at 0, B[2][6144] at 32768
#define SOA0 0
#define SOA1 16384
#define SOB0 32768
#define SOB1 (32768 + 6144)
#define SO_TOT (32768 + 12288)      // 45056

__global__ __launch_bounds__(NTHRO, 2)
void offset_gemm_kernel(const float* __restrict__ x,
                        const float* __restrict__ b_off)
{
    const uint32_t sb = smem_u32(smem_c);
    const int t    = threadIdx.x;
    const int wid  = t >> 5;
    const int lane = t & 31;
    const int m0g  = blockIdx.x * 128;
    const int wm   = wid * 16;

    float acc[6][4];
    #pragma unroll
    for (int j = 0; j < 6; j++)
        #pragma unroll
        for (int e = 0; e < 4; e++) acc[j][e] = 0.0f;

    float4 pa[8];     // prefetched A f32

    auto ldgA = [&](int c) {
        int kOff = 64 * c;
        #pragma unroll
        for (int i = 0; i < 4; i++) {
            int idx = t + i * NTHRO;
            int row = idx >> 3, c16 = idx & 7;
            const float4* src = (const float4*)(x + (size_t)(m0g + row) * 384 + kOff + c16 * 8);
            pa[2 * i]     = __ldg(src);
            pa[2 * i + 1] = __ldg(src + 1);
        }
    };
    auto stsA = [&](int buf) {
        char* base = smem_c + (buf ? SOA1 : SOA0);
        #pragma unroll
        for (int i = 0; i < 4; i++) {
            int idx = t + i * NTHRO;
            int row = idx >> 3, c16 = idx & 7;
            uint4 u;
            u.x = h2u(__floats2half2_rn(pa[2 * i].x,     pa[2 * i].y));
            u.y = h2u(__floats2half2_rn(pa[2 * i].z,     pa[2 * i].w));
            u.z = h2u(__floats2half2_rn(pa[2 * i + 1].x, pa[2 * i + 1].y));
            u.w = h2u(__floats2half2_rn(pa[2 * i + 1].z, pa[2 * i + 1].w));
            *(uint4*)(base + SWZ128(row * 128 + c16 * 16)) = u;
        }
    };
    auto cpB = [&](int c) {
        int kOff = 64 * c;
        uint32_t sB = sb + ((c & 1) ? SOB1 : SOB0);
        {
            int idx = t;
            int row = idx >> 3, c16 = idx & 7;
            cp_async16(sB + SWZ128(row * 128 + c16 * 16),
                       g_W + (size_t)row * 384 + kOff + c16 * 8);
        }
        if (t < 128) {
            int idx = t + 256;
            int row = idx >> 3, c16 = idx & 7;
            cp_async16(sB + SWZ128(row * 128 + c16 * 16),
                       g_W + (size_t)row * 384 + kOff + c16 * 8);
        }
    };

    // preamble: stage chunk 0
    ldgA(0); stsA(0);
    cpB(0); CP_COMMIT();

    for (int c = 0; c < OCHUNK; c++) {
        CP_WAIT(0);
        __syncthreads();   // B(c) + stsA(c) visible; prev compute done everywhere
        if (c + 1 < OCHUNK) {
            ldgA(c + 1);
            cpB(c + 1); CP_COMMIT();
        }

        int buf = c & 1;
        uint32_t sA = sb + (buf ? SOA1 : SOA0);
        uint32_t sB = sb + (buf ? SOB1 : SOB0);

        #pragma unroll
        for (int k16 = 0; k16 < 4; k16++) {
            int kb = k16 * 32;
            uint32_t a[4];
            {
                int row  = wm + (lane & 15);
                int colb = kb + ((lane & 16) ? 16 : 0);
                ldm_x4(a[0], a[1], a[2], a[3], sA + SWZ128(row * 128 + colb));
            }
            uint32_t bf[6][2];
            #pragma unroll
            for (int p = 0; p < 3; p++) {
                int grp  = lane >> 3;
                int nt   = p * 2 + (grp >> 1);
                int half = grp & 1;
                int row  = nt * 8 + (lane & 7);
                int colb = kb + half * 16;
                uint32_t r0, r1, r2, r3;
                ldm_x4(r0, r1, r2, r3, sB + SWZ128(row * 128 + colb));
                bf[p * 2][0] = r0;  bf[p * 2][1] = r1;
                bf[p * 2 + 1][0] = r2;  bf[p * 2 + 1][1] = r3;
            }
            #pragma unroll
            for (int j = 0; j < 6; j++)
                mma_fp16(acc[j], a, bf[j]);
        }
        // write A(c+1) into buffer (c+1)&1: its last readers ran in iteration
        // c-1, which completed before this iteration's __syncthreads.
        if (c + 1 < OCHUNK) stsA((c + 1) & 1);
    }

    // epilogue: + b_off, store float2
    #pragma unroll
    for (int j = 0; j < 6; j++) {
        int n = j * 8 + (lane & 3) * 2;
        float2 bias = __ldg((const float2*)(b_off + n));
        int m = m0g + wm + (lane >> 2);
        *(float2*)(g_Off + (size_t)m * 48 + n) =
            make_float2(acc[j][0] + bias.x, acc[j][1] + bias.y);
        *(float2*)(g_Off + (size_t)(m + 8) * 48 + n) =
            make_float2(acc[j][2] + bias.x, acc[j][3] + bias.y);
    }
}

// =============================================================================
// Kernel V: sampling — k-major output: thread (m,k) gathers 16 channels,
// stores one contiguous 32B run. No value smem, fully coalesced STG.
// CTA = 32 m rows x 24 k = 768 units over 256 threads (3 iterations).
// =============================================================================
#define TMV   32
#define NTHRV 256
#define SMV_TOT (TMV * 48 * 4)     // 6144 B offset stage

__global__ __launch_bounds__(NTHRV, 1)
void sampling_kernel(const float* __restrict__ x)
{
    float* s_off = (float*)smem_c;
    const int t = threadIdx.x;
    const size_t mbase = (size_t)blockIdx.x * TMV;
    const int b = (int)(mbase / LOUT);
    const int lout0 = (int)(mbase % LOUT);
    const float* xb = x + (size_t)b * LN * CN;

    // stage 32 x 48 offsets (384 float4)
    {
        const float4* src = (const float4*)(g_Off + mbase * 48);
        float4* dst = (float4*)s_off;
        dst[t] = __ldg(&src[t]);
        if (t < 128) dst[t + 256] = __ldg(&src[t + 256]);
    }
    __syncthreads();

    #pragma unroll
    for (int it = 0; it < 3; it++) {
        int j = t + it * NTHRV;       // 0..767
        int m = j / KN;
        int k = j % KN;
        float dy = s_off[m * 48 + 2 * k];
        float dx = s_off[m * 48 + 2 * k + 1];
        float wy = fmaxf(0.0f, 1.0f - fabsf(dy));
        float px = (float)((lout0 + m) * KN + k) + dx;
        bool valid = (px > -1.0f) && (px < (float)LN);
        float x0f = floorf(px);
        float lw = px - x0f;
        int i0 = (int)x0f;
        int i1 = i0 + 1;
        float w0 = (valid && i0 >= 0 && i0 < LN) ? (1.0f - lw) * wy : 0.0f;
        float w1 = (valid && i1 >= 0 && i1 < LN) ? lw * wy : 0.0f;
        int i0c = min(max(i0, 0), LN - 1);
        int i1c = min(max(i1, 0), LN - 1);
        const float4* p0 = (const float4*)(xb + (size_t)i0c * CN);
        const float4* p1 = (const float4*)(xb + (size_t)i1c * CN);
        uint4 u0, u1;
        {
            float4 a0 = __ldg(&p0[0]), b0 = __ldg(&p1[0]);
            float4 a1 = __ldg(&p0[1]), b1 = __ldg(&p1[1]);
            u0.x = h2u(__floats2half2_rn(a0.x * w0 + b0.x * w1, a0.y * w0 + b0.y * w1));
            u0.y = h2u(__floats2half2_rn(a0.z * w0 + b0.z * w1, a0.w * w0 + b0.w * w1));
            u0.z = h2u(__floats2half2_rn(a1.x * w0 + b1.x * w1, a1.y * w0 + b1.y * w1));
            u0.w = h2u(__floats2half2_rn(a1.z * w0 + b1.z * w1, a1.w * w0 + b1.w * w1));
        }
        {
            float4 a2 = __ldg(&p0[2]), b2 = __ldg(&p1[2]);
            float4 a3 = __ldg(&p0[3]), b3 = __ldg(&p1[3]);
            u1.x = h2u(__floats2half2_rn(a2.x * w0 + b2.x * w1, a2.y * w0 + b2.y * w1));
            u1.y = h2u(__floats2half2_rn(a2.z * w0 + b2.z * w1, a2.w * w0 + b2.w * w1));
            u1.z = h2u(__floats2half2_rn(a3.x * w0 + b3.x * w1, a3.y * w0 + b3.y * w1));
            u1.w = h2u(__floats2half2_rn(a3.z * w0 + b3.z * w1, a3.w * w0 + b3.w * w1));
        }
        uint4* dst = (uint4*)(g_A + (mbase + m) * 384 + k * 16);
        dst[0] = u0;
        dst[1] = u1;
    }
}

// =============================================================================
// Kernel G: main GEMM  out[49152][512] = g_A x g_B^T (k-major, 6 chunks)
// Single barrier per chunk; grid (n-fast) so 4 CTAs share each A tile in L2.
// =============================================================================
#define NTHR2 256
#define NCHUNK 6
#define SM2A0 0
#define SM2B0 16384
#define SM2A1 32768
#define SM2B1 49152
#define SM2_TOT 65536

__global__ __launch_bounds__(NTHR2, 2)
void gemm_mma_kernel(const float* __restrict__ b_def, float* __restrict__ out)
{
    const uint32_t sb = smem_u32(smem_c);
    const int t    = threadIdx.x;
    const int wid  = t >> 5;
    const int lane = t & 31;
    const int m0g  = blockIdx.y * 128;     // n-fast rasterization
    const int n0g  = blockIdx.x * 128;

    const int wm = (wid >> 2) * 64;
    const int wn = (wid & 3) * 32;

    const int prow = t >> 3;
    const int pc16 = t & 7;

    float acc[4][4][4];
    #pragma unroll
    for (int i = 0; i < 4; i++)
        #pragma unroll
        for (int j = 0; j < 4; j++)
            #pragma unroll
            for (int e = 0; e < 4; e++) acc[i][j][e] = 0.0f;

    auto prefetch = [&](int c) {
        int buf = c & 1;
        int kOff = 64 * c;
        uint32_t sA = sb + (buf ? SM2A1 : SM2A0);
        uint32_t sB = sb + (buf ? SM2B1 : SM2B0);
        #pragma unroll
        for (int i = 0; i < 4; i++) {
            int row = prow + i * 32;
            cp_async16(sA + SWZ128(row * 128 + pc16 * 16),
                       g_A + (size_t)(m0g + row) * 384 + kOff + pc16 * 8);
        }
        #pragma unroll
        for (int i = 0; i < 4; i++) {
            int row = prow + i * 32;
            cp_async16(sB + SWZ128(row * 128 + pc16 * 16),
                       g_B + (size_t)(n0g + row) * 384 + kOff + pc16 * 8);
        }
    };

    prefetch(0);
    CP_COMMIT();

    for (int c = 0; c < NCHUNK; c++) {
        CP_WAIT(0);
        __syncthreads();   // chunk c visible everywhere; prev compute finished
        if (c + 1 < NCHUNK) {
            // buffer (c+1)&1's last readers ran in iteration c-1, before the
            // barrier above — safe to overwrite while computing chunk c.
            prefetch(c + 1);
            CP_COMMIT();
        }

        int buf = c & 1;
        uint32_t sA = sb + (buf ? SM2A1 : SM2A0);
        uint32_t sB = sb + (buf ? SM2B1 : SM2B0);

        #pragma unroll
        for (int k16 = 0; k16 < 4; k16++) {
            int kb = k16 * 32;
            uint32_t a[4][4];
            #pragma unroll
            for (int i = 0; i < 4; i++) {
                int row  = wm + i * 16 + (lane & 15);
                int colb = kb + ((lane & 16) ? 16 : 0);
                ldm_x4(a[i][0], a[i][1], a[i][2], a[i][3],
                       sA + SWZ128(row * 128 + colb));
            }
            uint32_t bf[4][2];
            #pragma unroll
            for (int p = 0; p < 2; p++) {
                int grp  = lane >> 3;
                int nt   = p * 2 + (grp >> 1);
                int half = grp & 1;
                int row  = wn + nt * 8 + (lane & 7);
                int colb = kb + half * 16;
                uint32_t r0, r1, r2, r3;
                ldm_x4(r0, r1, r2, r3, sB + SWZ128(row * 128 + colb));
                bf[p * 2][0] = r0;  bf[p * 2][1] = r1;
                bf[p * 2 + 1][0] = r2;  bf[p * 2 + 1][1] = r3;
            }
            #pragma unroll
            for (int i = 0; i < 4; i++)
                #pragma unroll
                for (int j = 0; j < 4; j++)
                    mma_fp16(acc[i][j], a[i], bf[j]);
        }
    }

    #pragma unroll
    for (int j = 0; j < 4; j++) {
        int n = n0g + wn + j * 8 + (lane & 3) * 2;
        float2 bias = __ldg((const float2*)(b_def + n));
        #pragma unroll
        for (int i = 0; i < 4; i++) {
            int m = m0g + wm + i * 16 + (lane >> 2);
            float2 v0 = make_float2(acc[i][j][0] + bias.x, acc[i][j][1] + bias.y);
            float2 v1 = make_float2(acc[i][j][2] + bias.x, acc[i][j][3] + bias.y);
            *(float2*)(out + (size_t)m * DN + n) = v0;
            *(float2*)(out + (size_t)(m + 8) * DN + n) = v1;
        }
    }
}

// =============================================================================
extern "C" void kernel_launch(void* const* d_in, const int* in_sizes, int n_in,
                              void* d_out, int out_size)
{
    const float* x     = (const float*)d_in[0];
    const float* w_off = (const float*)d_in[1];
    const float* b_off = (const float*)d_in[2];
    const float* w_def = (const float*)d_in[3];
    const float* b_def = (const float*)d_in[4];
    float* out = (float*)d_out;

    static bool attr_set = false;
    if (!attr_set) {
        cudaFuncSetAttribute(gemm_mma_kernel,
                             cudaFuncAttributeMaxDynamicSharedMemorySize, SM2_TOT);
        attr_set = true;
    }

    split_weights_kernel<<<((DN + 48) * CKN + 255) / 256, 256>>>(w_def, w_off);
    offset_gemm_kernel<<<MTOT / 128, NTHRO, SO_TOT>>>(x, b_off);
    sampling_kernel<<<MTOT / TMV, NTHRV, SMV_TOT>>>(x);
    dim3 grid2(DN / 128, MTOT / 128);     // n-fast: 4 x 384
    gemm_mma_kernel<<<grid2, NTHR2, SM2_TOT>>>(b_def, out);
}

// round 16
// speedup vs baseline: 1.5388x; 1.4697x over previous
#include <cuda_runtime.h>
#include <cuda_bf16.h>
#include <cuda_fp16.h>
#include <cstdint>

#define BN    32
#define LN    36864
#define CN    16
#define KN    24
#define LOUT  1536
#define DN    512
#define CKN   384
#define MTOT  (BN * LOUT)      // 49152

// single TU-wide dynamic smem symbol
extern __shared__ char smem_c[];

// ---------------- global scratch (ALL k-major: ck' = k*16 + c) ---------------
__device__ __half g_A [(size_t)MTOT * 384];   // sampled values, k-major
__device__ __half g_B [(size_t)DN * 384];     // w_def fp16, k-major
__device__ __half g_W [(size_t)48 * 384];     // w_off fp16, k-major

// ---------------- PTX helpers ------------------------------------------------
__device__ __forceinline__ uint32_t smem_u32(const void* p) {
    return (uint32_t)__cvta_generic_to_shared(p);
}

#define SWZ128(off) ((off) ^ (((off) >> 3) & 0x70))

__device__ __forceinline__ void cp_async16(uint32_t saddr, const void* gptr) {
    asm volatile("cp.async.cg.shared.global [%0], [%1], 16;" :: "r"(saddr), "l"(gptr));
}
#define CP_COMMIT() asm volatile("cp.async.commit_group;" ::: "memory")
#define CP_WAIT(N)  asm volatile("cp.async.wait_group %0;" :: "n"(N) : "memory")

__device__ __forceinline__ void ldm_x4(uint32_t& r0, uint32_t& r1, uint32_t& r2,
                                       uint32_t& r3, uint32_t addr) {
    asm volatile("ldmatrix.sync.aligned.m8n8.x4.shared.b16 {%0,%1,%2,%3}, [%4];"
                 : "=r"(r0), "=r"(r1), "=r"(r2), "=r"(r3) : "r"(addr));
}
__device__ __forceinline__ void mma_fp16(float* d, const uint32_t* a, const uint32_t* b) {
    asm volatile(
        "mma.sync.aligned.m16n8k16.row.col.f32.f16.f16.f32 "
        "{%0,%1,%2,%3}, {%4,%5,%6,%7}, {%8,%9}, {%0,%1,%2,%3};"
        : "+f"(d[0]), "+f"(d[1]), "+f"(d[2]), "+f"(d[3])
        : "r"(a[0]), "r"(a[1]), "r"(a[2]), "r"(a[3]), "r"(b[0]), "r"(b[1]));
}
__device__ __forceinline__ uint32_t h2u(__half2 h) { return *(uint32_t*)&h; }

// =============================================================================
// Kernel S: transpose weights to k-major (coalesced read AND write via smem)
// one block = one output row (384 elems), 384 threads.
// =============================================================================
__global__ void split_weights_kernel(const float* __restrict__ w_def,
                                     const float* __restrict__ w_off) {
    float* s = (float*)smem_c;
    const int row = blockIdx.x;
    const int t = threadIdx.x;
    const float* src = (row < DN) ? (w_def + (size_t)row * CKN)
                                  : (w_off + (size_t)(row - DN) * CKN);
    __half* dst = (row < DN) ? (g_B + (size_t)row * CKN)
                             : (g_W + (size_t)(row - DN) * CKN);
    s[t] = __ldg(&src[t]);          // coalesced read (c-major source)
    __syncthreads();
    int k = t >> 4, c = t & 15;     // output index t = k*16+c
    dst[t] = __float2half_rn(s[c * KN + k]);   // coalesced write
}

// =============================================================================
// Kernel P: FUSED offsets + sampling.
// Phase 1: offsets GEMM for this CTA's 128 rows -> smem (tensor cores).
// Phase 2: bilinear gather from x -> g_A (k-major, coalesced 32B stores).
// =============================================================================
#define NTHRP 256
#define PCHUNK 6
// smem bytes: A[2][16384] 0..32768, B[2][6144] 32768..45056, OFF 45056..69632
#define SPA0 0
#define SPA1 16384
#define SPB0 32768
#define SPB1 (32768 + 6144)
#define SP_OFF 45056
#define SP_TOT (45056 + 128 * 48 * 4)      // 69632

__global__ __launch_bounds__(NTHRP, 2)
void producer_kernel(const float* __restrict__ x,
                     const float* __restrict__ b_off)
{
    const uint32_t sb = smem_u32(smem_c);
    float* s_off = (float*)(smem_c + SP_OFF);
    const int t    = threadIdx.x;
    const int wid  = t >> 5;
    const int lane = t & 31;
    const int m0g  = blockIdx.x * 128;
    const int wm   = wid * 16;

    const int b = m0g / LOUT;                 // 128 | 1536: no tile crosses batch
    const int lr0 = m0g % LOUT;
    const float* xb = x + (size_t)b * LN * CN;

    // ---------------- Phase 1: offsets GEMM (x_win fp32 -> fp16 staging) ------
    {
        float acc[6][4];
        #pragma unroll
        for (int j = 0; j < 6; j++)
            #pragma unroll
            for (int e = 0; e < 4; e++) acc[j][e] = 0.0f;

        float4 pa[8];

        auto ldgA = [&](int c) {
            int kOff = 64 * c;
            #pragma unroll
            for (int i = 0; i < 4; i++) {
                int idx = t + i * NTHRP;
                int row = idx >> 3, c16 = idx & 7;
                const float4* src = (const float4*)(x + (size_t)(m0g + row) * 384 + kOff + c16 * 8);
                pa[2 * i]     = __ldg(src);
                pa[2 * i + 1] = __ldg(src + 1);
            }
        };
        auto stsA = [&](int buf) {
            char* base = smem_c + (buf ? SPA1 : SPA0);
            #pragma unroll
            for (int i = 0; i < 4; i++) {
                int idx = t + i * NTHRP;
                int row = idx >> 3, c16 = idx & 7;
                uint4 u;
                u.x = h2u(__floats2half2_rn(pa[2 * i].x,     pa[2 * i].y));
                u.y = h2u(__floats2half2_rn(pa[2 * i].z,     pa[2 * i].w));
                u.z = h2u(__floats2half2_rn(pa[2 * i + 1].x, pa[2 * i + 1].y));
                u.w = h2u(__floats2half2_rn(pa[2 * i + 1].z, pa[2 * i + 1].w));
                *(uint4*)(base + SWZ128(row * 128 + c16 * 16)) = u;
            }
        };
        auto cpB = [&](int c) {
            int kOff = 64 * c;
            uint32_t sB = sb + ((c & 1) ? SPB1 : SPB0);
            {
                int row = t >> 3, c16 = t & 7;
                cp_async16(sB + SWZ128(row * 128 + c16 * 16),
                           g_W + (size_t)row * 384 + kOff + c16 * 8);
            }
            if (t < 128) {
                int idx = t + 256;
                int row = idx >> 3, c16 = idx & 7;
                cp_async16(sB + SWZ128(row * 128 + c16 * 16),
                           g_W + (size_t)row * 384 + kOff + c16 * 8);
            }
        };

        ldgA(0); stsA(0);
        cpB(0); CP_COMMIT();

        for (int c = 0; c < PCHUNK; c++) {
            CP_WAIT(0);
            __syncthreads();
            if (c + 1 < PCHUNK) {
                ldgA(c + 1);
                cpB(c + 1); CP_COMMIT();
            }

            int buf = c & 1;
            uint32_t sA = sb + (buf ? SPA1 : SPA0);
            uint32_t sB = sb + (buf ? SPB1 : SPB0);

            #pragma unroll
            for (int k16 = 0; k16 < 4; k16++) {
                int kb = k16 * 32;
                uint32_t a[4];
                {
                    int row  = wm + (lane & 15);
                    int colb = kb + ((lane & 16) ? 16 : 0);
                    ldm_x4(a[0], a[1], a[2], a[3], sA + SWZ128(row * 128 + colb));
                }
                uint32_t bf[6][2];
                #pragma unroll
                for (int p = 0; p < 3; p++) {
                    int grp  = lane >> 3;
                    int nt   = p * 2 + (grp >> 1);
                    int half = grp & 1;
                    int row  = nt * 8 + (lane & 7);
                    int colb = kb + half * 16;
                    uint32_t r0, r1, r2, r3;
                    ldm_x4(r0, r1, r2, r3, sB + SWZ128(row * 128 + colb));
                    bf[p * 2][0] = r0;  bf[p * 2][1] = r1;
                    bf[p * 2 + 1][0] = r2;  bf[p * 2 + 1][1] = r3;
                }
                #pragma unroll
                for (int j = 0; j < 6; j++)
                    mma_fp16(acc[j], a, bf[j]);
            }
            if (c + 1 < PCHUNK) stsA((c + 1) & 1);
        }

        // epilogue -> smem offsets (+bias)
        #pragma unroll
        for (int j = 0; j < 6; j++) {
            int n = j * 8 + (lane & 3) * 2;
            float2 bias = __ldg((const float2*)(b_off + n));
            int ml = wm + (lane >> 2);
            *(float2*)(s_off + ml * 48 + n) =
                make_float2(acc[j][0] + bias.x, acc[j][1] + bias.y);
            *(float2*)(s_off + (ml + 8) * 48 + n) =
                make_float2(acc[j][2] + bias.x, acc[j][3] + bias.y);
        }
    }
    __syncthreads();

    // ---------------- Phase 2: bilinear sampling -> g_A ------------------------
    #pragma unroll
    for (int it = 0; it < 12; it++) {
        int j = t + it * NTHRP;       // 0..3071
        int m = j / KN;
        int k = j % KN;
        float dy = s_off[m * 48 + 2 * k];
        float dx = s_off[m * 48 + 2 * k + 1];
        float wy = fmaxf(0.0f, 1.0f - fabsf(dy));
        float px = (float)((lr0 + m) * KN + k) + dx;
        bool valid = (px > -1.0f) && (px < (float)LN);
        float x0f = floorf(px);
        float lw = px - x0f;
        int i0 = (int)x0f;
        int i1 = i0 + 1;
        float w0 = (valid && i0 >= 0 && i0 < LN) ? (1.0f - lw) * wy : 0.0f;
        float w1 = (valid && i1 >= 0 && i1 < LN) ? lw * wy : 0.0f;
        int i0c = min(max(i0, 0), LN - 1);
        int i1c = min(max(i1, 0), LN - 1);
        const float4* p0 = (const float4*)(xb + (size_t)i0c * CN);
        const float4* p1 = (const float4*)(xb + (size_t)i1c * CN);
        uint4 u0, u1;
        {
            float4 a0 = __ldg(&p0[0]), b0 = __ldg(&p1[0]);
            float4 a1 = __ldg(&p0[1]), b1 = __ldg(&p1[1]);
            u0.x = h2u(__floats2half2_rn(a0.x * w0 + b0.x * w1, a0.y * w0 + b0.y * w1));
            u0.y = h2u(__floats2half2_rn(a0.z * w0 + b0.z * w1, a0.w * w0 + b0.w * w1));
            u0.z = h2u(__floats2half2_rn(a1.x * w0 + b1.x * w1, a1.y * w0 + b1.y * w1));
            u0.w = h2u(__floats2half2_rn(a1.z * w0 + b1.z * w1, a1.w * w0 + b1.w * w1));
        }
        {
            float4 a2 = __ldg(&p0[2]), b2 = __ldg(&p1[2]);
            float4 a3 = __ldg(&p0[3]), b3 = __ldg(&p1[3]);
            u1.x = h2u(__floats2half2_rn(a2.x * w0 + b2.x * w1, a2.y * w0 + b2.y * w1));
            u1.y = h2u(__floats2half2_rn(a2.z * w0 + b2.z * w1, a2.w * w0 + b2.w * w1));
            u1.z = h2u(__floats2half2_rn(a3.x * w0 + b3.x * w1, a3.y * w0 + b3.y * w1));
            u1.w = h2u(__floats2half2_rn(a3.z * w0 + b3.z * w1, a3.w * w0 + b3.w * w1));
        }
        uint4* dst = (uint4*)(g_A + (size_t)(m0g + m) * 384 + k * 16);
        dst[0] = u0;
        dst[1] = u1;
    }
}

// =============================================================================
// Kernel G: main GEMM  out[49152][512] = g_A x g_B^T (k-major, 6 chunks)
// 3-stage cp.async pipeline; n-fast grid (4 CTAs share each A tile in L2).
// =============================================================================
#define NTHR2 256
#define NCHUNK 6
#define SM2_ASZ 16384
#define SM2_B0  49152
#define SM2_TOT 98304

__global__ __launch_bounds__(NTHR2, 2)
void gemm_mma_kernel(const float* __restrict__ b_def, float* __restrict__ out)
{
    const uint32_t sb = smem_u32(smem_c);
    const int t    = threadIdx.x;
    const int wid  = t >> 5;
    const int lane = t & 31;
    const int m0g  = blockIdx.y * 128;     // n-fast rasterization
    const int n0g  = blockIdx.x * 128;

    const int wm = (wid >> 2) * 64;
    const int wn = (wid & 3) * 32;

    const int prow = t >> 3;
    const int pc16 = t & 7;

    float acc[4][4][4];
    #pragma unroll
    for (int i = 0; i < 4; i++)
        #pragma unroll
        for (int j = 0; j < 4; j++)
            #pragma unroll
            for (int e = 0; e < 4; e++) acc[i][j][e] = 0.0f;

    auto prefetch = [&](int c) {
        int buf = c % 3;
        int kOff = 64 * c;
        uint32_t sA = sb + buf * SM2_ASZ;
        uint32_t sB = sb + SM2_B0 + buf * SM2_ASZ;
        #pragma unroll
        for (int i = 0; i < 4; i++) {
            int row = prow + i * 32;
            cp_async16(sA + SWZ128(row * 128 + pc16 * 16),
                       g_A + (size_t)(m0g + row) * 384 + kOff + pc16 * 8);
        }
        #pragma unroll
        for (int i = 0; i < 4; i++) {
            int row = prow + i * 32;
            cp_async16(sB + SWZ128(row * 128 + pc16 * 16),
                       g_B + (size_t)(n0g + row) * 384 + kOff + pc16 * 8);
        }
    };

    prefetch(0); CP_COMMIT();
    prefetch(1); CP_COMMIT();

    for (int c = 0; c < NCHUNK; c++) {
        if (c < NCHUNK - 1) { CP_WAIT(1); } else { CP_WAIT(0); }
        __syncthreads();   // chunk c resident everywhere; iter c-1 compute done
        if (c + 2 < NCHUNK) {
            // buffer (c+2)%3 == (c-1)%3: last read in iteration c-1, which all
            // threads finished before the barrier above.
            prefetch(c + 2);
            CP_COMMIT();
        }

        int buf = c % 3;
        uint32_t sA = sb + buf * SM2_ASZ;
        uint32_t sB = sb + SM2_B0 + buf * SM2_ASZ;

        #pragma unroll
        for (int k16 = 0; k16 < 4; k16++) {
            int kb = k16 * 32;
            uint32_t a[4][4];
            #pragma unroll
            for (int i = 0; i < 4; i++) {
                int row  = wm + i * 16 + (lane & 15);
                int colb = kb + ((lane & 16) ? 16 : 0);
                ldm_x4(a[i][0], a[i][1], a[i][2], a[i][3],
                       sA + SWZ128(row * 128 + colb));
            }
            uint32_t bf[4][2];
            #pragma unroll
            for (int p = 0; p < 2; p++) {
                int grp  = lane >> 3;
                int nt   = p * 2 + (grp >> 1);
                int half = grp & 1;
                int row  = wn + nt * 8 + (lane & 7);
                int colb = kb + half * 16;
                uint32_t r0, r1, r2, r3;
                ldm_x4(r0, r1, r2, r3, sB + SWZ128(row * 128 + colb));
                bf[p * 2][0] = r0;  bf[p * 2][1] = r1;
                bf[p * 2 + 1][0] = r2;  bf[p * 2 + 1][1] = r3;
            }
            #pragma unroll
            for (int i = 0; i < 4; i++)
                #pragma unroll
                for (int j = 0; j < 4; j++)
                    mma_fp16(acc[i][j], a[i], bf[j]);
        }
    }

    #pragma unroll
    for (int j = 0; j < 4; j++) {
        int n = n0g + wn + j * 8 + (lane & 3) * 2;
        float2 bias = __ldg((const float2*)(b_def + n));
        #pragma unroll
        for (int i = 0; i < 4; i++) {
            int m = m0g + wm + i * 16 + (lane >> 2);
            float2 v0 = make_float2(acc[i][j][0] + bias.x, acc[i][j][1] + bias.y);
            float2 v1 = make_float2(acc[i][j][2] + bias.x, acc[i][j][3] + bias.y);
            *(float2*)(out + (size_t)m * DN + n) = v0;
            *(float2*)(out + (size_t)(m + 8) * DN + n) = v1;
        }
    }
}

// =============================================================================
extern "C" void kernel_launch(void* const* d_in, const int* in_sizes, int n_in,
                              void* d_out, int out_size)
{
    const float* x     = (const float*)d_in[0];
    const float* w_off = (const float*)d_in[1];
    const float* b_off = (const float*)d_in[2];
    const float* w_def = (const float*)d_in[3];
    const float* b_def = (const float*)d_in[4];
    float* out = (float*)d_out;

    static bool attr_set = false;
    if (!attr_set) {
        cudaFuncSetAttribute(producer_kernel,
                             cudaFuncAttributeMaxDynamicSharedMemorySize, SP_TOT);
        cudaFuncSetAttribute(gemm_mma_kernel,
                             cudaFuncAttributeMaxDynamicSharedMemorySize, SM2_TOT);
        attr_set = true;
    }

    split_weights_kernel<<<DN + 48, CKN, CKN * sizeof(float)>>>(w_def, w_off);
    producer_kernel<<<MTOT / 128, NTHRP, SP_TOT>>>(x, b_off);
    dim3 grid2(DN / 128, MTOT / 128);     // n-fast: 4 x 384
    gemm_mma_kernel<<<grid2, NTHR2, SM2_TOT>>>(b_def, out);
}